// round 1
// baseline (speedup 1.0000x reference)
#include <cuda_runtime.h>
#include <math.h>

#define S 2048
#define BATCH 2
#define D 1024
#define H 16
#define HD 64
#define FFN_DIM 4096
#define T (S*BATCH)          // 4096 token rows
#define NEGV -1e9f

// ---------------- scratch (device globals; no allocation allowed) ----------------
__device__ float g_q[(size_t)T*D];
__device__ float g_k[(size_t)T*D];
__device__ float g_v[(size_t)T*D];
__device__ float g_ao[(size_t)T*D];
__device__ float g_x1[(size_t)T*D];
__device__ float g_y[(size_t)T*D];
__device__ float g_h[(size_t)T*FFN_DIM];
__device__ float g_attn[(size_t)BATCH*H*S*S];   // raw scores / fallback probs (512 MB)

// ---------------- generic GEMM: C[M,N] = A[M,K] @ W[K,N] + bias, epilogue ----------------
// BM=128, BN=64, BK=16, 256 threads, 8x4 per thread.
// EPI: 0 = bias, 1 = (bias)*scale, 2 = gelu(bias-added)
template<int EPI>
__global__ __launch_bounds__(256) void gemm_kernel(
    const float* __restrict__ A, const float* __restrict__ W,
    const float* __restrict__ bias, float* __restrict__ C,
    int N, int K, float scale)
{
    __shared__ float As[128][16];
    __shared__ float Bs[16][64];
    const int m0 = blockIdx.y * 128;
    const int n0 = blockIdx.x * 64;
    const int tid = threadIdx.x;
    const int tx = tid & 15;       // 0..15 -> 4 cols each
    const int ty = tid >> 4;       // 0..15 -> 8 rows each
    float acc[8][4] = {};

    for (int k0 = 0; k0 < K; k0 += 16) {
        #pragma unroll
        for (int i = tid; i < 128*16; i += 256) {
            int r = i >> 4, c = i & 15;
            As[r][c] = A[(size_t)(m0 + r) * K + k0 + c];
        }
        #pragma unroll
        for (int i = tid; i < 16*64; i += 256) {
            int r = i >> 6, c = i & 63;
            Bs[r][c] = W[(size_t)(k0 + r) * N + n0 + c];
        }
        __syncthreads();
        #pragma unroll
        for (int kk = 0; kk < 16; kk++) {
            float4 bv = *(const float4*)&Bs[kk][tx * 4];
            #pragma unroll
            for (int i = 0; i < 8; i++) {
                float a = As[ty * 8 + i][kk];
                acc[i][0] += a * bv.x;
                acc[i][1] += a * bv.y;
                acc[i][2] += a * bv.z;
                acc[i][3] += a * bv.w;
            }
        }
        __syncthreads();
    }

    float4 b4 = *(const float4*)&bias[n0 + tx * 4];
    #pragma unroll
    for (int i = 0; i < 8; i++) {
        float4 r;
        r.x = acc[i][0] + b4.x;
        r.y = acc[i][1] + b4.y;
        r.z = acc[i][2] + b4.z;
        r.w = acc[i][3] + b4.w;
        if (EPI == 1) { r.x *= scale; r.y *= scale; r.z *= scale; r.w *= scale; }
        if (EPI == 2) {
            r.x = 0.5f * r.x * (1.0f + erff(r.x * 0.70710678118654752f));
            r.y = 0.5f * r.y * (1.0f + erff(r.y * 0.70710678118654752f));
            r.z = 0.5f * r.z * (1.0f + erff(r.z * 0.70710678118654752f));
            r.w = 0.5f * r.w * (1.0f + erff(r.w * 0.70710678118654752f));
        }
        *(float4*)&C[(size_t)(m0 + ty * 8 + i) * N + n0 + tx * 4] = r;
    }
}

// ---------------- QK^T: scores[n, qi, ki] = sum_d Q[n,qi,d]*K[n,ki,d] ----------------
// q,k are [S,B,D] matrices; head (b,h) uses cols [h*64, h*64+64) of rows (s*B + b).
// tile: 128 qi x 64 ki, K=64 processed in two 32-chunks (static smem budget).
__global__ __launch_bounds__(256) void qk_kernel(
    const float* __restrict__ q, const float* __restrict__ k, float* __restrict__ out)
{
    __shared__ float Qs[128][32];
    __shared__ float Ks[64][33];
    const int n = blockIdx.z;
    const int b = n >> 4, h = n & 15;
    const int q0 = blockIdx.y * 128;
    const int k0 = blockIdx.x * 64;
    const int tid = threadIdx.x;
    const int tx = tid & 15, ty = tid >> 4;
    float acc[8][4] = {};

    for (int d0 = 0; d0 < 64; d0 += 32) {
        #pragma unroll
        for (int i = tid; i < 128*32; i += 256) {
            int r = i >> 5, c = i & 31;
            Qs[r][c] = q[((size_t)(q0 + r) * BATCH + b) * D + h * 64 + d0 + c];
        }
        #pragma unroll
        for (int i = tid; i < 64*32; i += 256) {
            int r = i >> 5, c = i & 31;
            Ks[r][c] = k[((size_t)(k0 + r) * BATCH + b) * D + h * 64 + d0 + c];
        }
        __syncthreads();
        #pragma unroll
        for (int d = 0; d < 32; d++) {
            float kb[4];
            #pragma unroll
            for (int j = 0; j < 4; j++) kb[j] = Ks[tx * 4 + j][d];
            #pragma unroll
            for (int i = 0; i < 8; i++) {
                float a = Qs[ty * 8 + i][d];
                acc[i][0] += a * kb[0];
                acc[i][1] += a * kb[1];
                acc[i][2] += a * kb[2];
                acc[i][3] += a * kb[3];
            }
        }
        __syncthreads();
    }

    #pragma unroll
    for (int i = 0; i < 8; i++) {
        float4 r = make_float4(acc[i][0], acc[i][1], acc[i][2], acc[i][3]);
        *(float4*)&out[(size_t)n * S * S + (size_t)(q0 + ty * 8 + i) * S + k0 + tx * 4] = r;
    }
}

// ---------------- softmax over last axis (+key padding mask) ----------------
// one block (256 thr) per (n, qi) row of length S=2048. in/out may alias.
__global__ __launch_bounds__(256) void softmax_kernel(
    const float* __restrict__ in, const unsigned char* __restrict__ mask,
    float* __restrict__ out)
{
    const size_t row = blockIdx.x;
    const int n = (int)(row >> 11);    // / S
    const int b = n >> 4;              // / H
    const float* ip = in + row * (size_t)S;
    float* op = out + row * (size_t)S;
    const int tid = threadIdx.x;

    float vals[8];
    float mx = -3.4e38f;
    #pragma unroll
    for (int i = 0; i < 8; i++) {
        int idx = tid + (i << 8);
        float mterm = mask[(size_t)b * S + idx] ? NEGV : 0.0f;
        float v = ip[idx] + mterm;
        vals[i] = v;
        mx = fmaxf(mx, v);
    }
    __shared__ float sh[256];
    sh[tid] = mx;
    __syncthreads();
    for (int st = 128; st > 0; st >>= 1) {
        if (tid < st) sh[tid] = fmaxf(sh[tid], sh[tid + st]);
        __syncthreads();
    }
    mx = sh[0];
    __syncthreads();

    float sum = 0.0f;
    #pragma unroll
    for (int i = 0; i < 8; i++) {
        vals[i] = __expf(vals[i] - mx);
        sum += vals[i];
    }
    sh[tid] = sum;
    __syncthreads();
    for (int st = 128; st > 0; st >>= 1) {
        if (tid < st) sh[tid] += sh[tid + st];
        __syncthreads();
    }
    float inv = 1.0f / sh[0];
    #pragma unroll
    for (int i = 0; i < 8; i++)
        op[tid + (i << 8)] = vals[i] * inv;
}

// ---------------- P @ V : ao[q, b, h*64+d] = sum_ki P[n,q,ki] * V[ki,b,h*64+d] ----------------
__global__ __launch_bounds__(256) void av_kernel(
    const float* __restrict__ P, const float* __restrict__ v, float* __restrict__ ao)
{
    __shared__ float Ps[128][16];
    __shared__ float Vs[16][64];
    const int n = blockIdx.y;
    const int b = n >> 4, h = n & 15;
    const int q0 = blockIdx.x * 128;
    const int tid = threadIdx.x;
    const int tx = tid & 15, ty = tid >> 4;
    const float* Pn = P + (size_t)n * S * S;
    float acc[8][4] = {};

    for (int k0 = 0; k0 < S; k0 += 16) {
        #pragma unroll
        for (int i = tid; i < 128*16; i += 256) {
            int r = i >> 4, c = i & 15;
            Ps[r][c] = Pn[(size_t)(q0 + r) * S + k0 + c];
        }
        #pragma unroll
        for (int i = tid; i < 16*64; i += 256) {
            int r = i >> 6, c = i & 63;
            Vs[r][c] = v[((size_t)(k0 + r) * BATCH + b) * D + h * 64 + c];
        }
        __syncthreads();
        #pragma unroll
        for (int kk = 0; kk < 16; kk++) {
            float4 bv = *(const float4*)&Vs[kk][tx * 4];
            #pragma unroll
            for (int i = 0; i < 8; i++) {
                float a = Ps[ty * 8 + i][kk];
                acc[i][0] += a * bv.x;
                acc[i][1] += a * bv.y;
                acc[i][2] += a * bv.z;
                acc[i][3] += a * bv.w;
            }
        }
        __syncthreads();
    }

    #pragma unroll
    for (int i = 0; i < 8; i++) {
        size_t o = ((size_t)(q0 + ty * 8 + i) * BATCH + b) * D + h * 64 + tx * 4;
        *(float4*)&ao[o] = make_float4(acc[i][0], acc[i][1], acc[i][2], acc[i][3]);
    }
}

// ---------------- layernorm(resid + y) * g + beta, rows of D=1024 ----------------
__global__ __launch_bounds__(256) void ln_kernel(
    const float* __restrict__ resid, const float* __restrict__ y,
    const float* __restrict__ g, const float* __restrict__ beta,
    float* __restrict__ out)
{
    const int row = blockIdx.x;
    const int tid = threadIdx.x;
    float4 a = ((const float4*)(resid + (size_t)row * D))[tid];
    float4 c = ((const float4*)(y + (size_t)row * D))[tid];
    float v0 = a.x + c.x, v1 = a.y + c.y, v2 = a.z + c.z, v3 = a.w + c.w;

    __shared__ float sh[256], sh2[256];
    sh[tid]  = v0 + v1 + v2 + v3;
    sh2[tid] = v0*v0 + v1*v1 + v2*v2 + v3*v3;
    __syncthreads();
    for (int st = 128; st > 0; st >>= 1) {
        if (tid < st) { sh[tid] += sh[tid + st]; sh2[tid] += sh2[tid + st]; }
        __syncthreads();
    }
    float mean = sh[0] * (1.0f / D);
    float var  = sh2[0] * (1.0f / D) - mean * mean;
    float rstd = rsqrtf(var + 1e-5f);

    float4 g4 = ((const float4*)g)[tid];
    float4 b4 = ((const float4*)beta)[tid];
    float4 o;
    o.x = (v0 - mean) * rstd * g4.x + b4.x;
    o.y = (v1 - mean) * rstd * g4.y + b4.y;
    o.z = (v2 - mean) * rstd * g4.z + b4.z;
    o.w = (v3 - mean) * rstd * g4.w + b4.w;
    ((float4*)(out + (size_t)row * D))[tid] = o;
}

// ---------------- launcher ----------------
extern "C" void kernel_launch(void* const* d_in, const int* in_sizes, int n_in,
                              void* d_out, int out_size)
{
    const float* x    = (const float*)d_in[0];
    const unsigned char* mask = (const unsigned char*)d_in[1];
    const float* Wq   = (const float*)d_in[2];
    const float* bq   = (const float*)d_in[3];
    const float* Wk   = (const float*)d_in[4];
    const float* bk   = (const float*)d_in[5];
    const float* Wv   = (const float*)d_in[6];
    const float* bv   = (const float*)d_in[7];
    const float* Wo   = (const float*)d_in[8];
    const float* bo   = (const float*)d_in[9];
    const float* ln1g = (const float*)d_in[10];
    const float* ln1b = (const float*)d_in[11];
    const float* W1   = (const float*)d_in[12];
    const float* b1   = (const float*)d_in[13];
    const float* W2   = (const float*)d_in[14];
    const float* b2   = (const float*)d_in[15];
    const float* ln2g = (const float*)d_in[16];
    const float* ln2b = (const float*)d_in[17];

    float *q, *k, *v, *ao, *x1, *y, *h, *attn;
    cudaGetSymbolAddress((void**)&q,  g_q);
    cudaGetSymbolAddress((void**)&k,  g_k);
    cudaGetSymbolAddress((void**)&v,  g_v);
    cudaGetSymbolAddress((void**)&ao, g_ao);
    cudaGetSymbolAddress((void**)&x1, g_x1);
    cudaGetSymbolAddress((void**)&y,  g_y);
    cudaGetSymbolAddress((void**)&h,  g_h);
    cudaGetSymbolAddress((void**)&attn, g_attn);

    const long long X  = (long long)T * D;                    // 4,194,304
    const long long AW = (long long)BATCH * H * (long long)S * S;  // 134,217,728
    float* xout;
    float* attnout;
    if ((long long)out_size >= X + AW) {          // (x, attn_weights) concatenated
        xout = (float*)d_out;
        attnout = (float*)d_out + X;
    } else if ((long long)out_size == AW) {       // attn only (unlikely)
        attnout = (float*)d_out;
        xout = ao;                                 // scratch; ao free by then
    } else {                                       // x only
        xout = (float*)d_out;
        attnout = attn;                            // softmax runs in place
    }

    dim3 blk(256);
    const float scaling = 0.125f;                  // hd^-0.5, hd=64

    // QKV projections
    gemm_kernel<1><<<dim3(D / 64, T / 128), blk>>>(x, Wq, bq, q, D, D, scaling);
    gemm_kernel<0><<<dim3(D / 64, T / 128), blk>>>(x, Wk, bk, k, D, D, 1.0f);
    gemm_kernel<0><<<dim3(D / 64, T / 128), blk>>>(x, Wv, bv, v, D, D, 1.0f);

    // attention
    qk_kernel<<<dim3(S / 64, S / 128, BATCH * H), blk>>>(q, k, attn);
    softmax_kernel<<<dim3(BATCH * H * S), blk>>>(attn, mask, attnout);
    av_kernel<<<dim3(S / 128, BATCH * H), blk>>>(attnout, v, ao);

    // output projection + residual LN1
    gemm_kernel<0><<<dim3(D / 64, T / 128), blk>>>(ao, Wo, bo, y, D, D, 1.0f);
    ln_kernel<<<dim3(T), blk>>>(x, y, ln1g, ln1b, x1);

    // FFN + residual LN2
    gemm_kernel<2><<<dim3(FFN_DIM / 64, T / 128), blk>>>(x1, W1, b1, h, FFN_DIM, D, 1.0f);
    gemm_kernel<0><<<dim3(D / 64, T / 128), blk>>>(h, W2, b2, y, D, FFN_DIM, 1.0f);
    ln_kernel<<<dim3(T), blk>>>(x1, y, ln2g, ln2b, xout);
}

// round 2
// speedup vs baseline: 1.1546x; 1.1546x over previous
#include <cuda_runtime.h>
#include <math.h>
#include <stdint.h>

#define S 2048
#define BATCH 2
#define D 1024
#define H 16
#define FFN_DIM 4096
#define T (S*BATCH)          // 4096 token rows
#define NEGV -1e9f

// ---------------- scratch (device globals; no allocation allowed) ----------------
__device__ float g_q[(size_t)T*D];
__device__ float g_k[(size_t)T*D];
__device__ float g_v[(size_t)T*D];
__device__ float g_ao[(size_t)T*D];
__device__ float g_x1[(size_t)T*D];
__device__ float g_y[(size_t)T*D];
__device__ float g_h[(size_t)T*FFN_DIM];
__device__ float g_attn[(size_t)BATCH*H*S*S];   // raw scores / fallback probs

// ---------------- tf32 helpers ----------------
__device__ __forceinline__ float to_tf32(float x) {
    uint32_t u;
    asm("cvt.rna.tf32.f32 %0, %1;" : "=r"(u) : "f"(x));
    return __uint_as_float(u);
}

__device__ __forceinline__ void mma8(float* c, const uint32_t* a, const uint32_t* b) {
    asm("mma.sync.aligned.m16n8k8.row.col.f32.tf32.tf32.f32 "
        "{%0,%1,%2,%3},{%4,%5,%6,%7},{%8,%9},{%0,%1,%2,%3};"
        : "+f"(c[0]), "+f"(c[1]), "+f"(c[2]), "+f"(c[3])
        : "r"(a[0]), "r"(a[1]), "r"(a[2]), "r"(a[3]),
          "r"(b[0]), "r"(b[1]));
}

// =====================================================================
// tf32 MMA GEMM: C[M,N] = A[M,K] @ B[K,N] (+bias, epilogue)
//   BM=128 fixed, BN in {128,64}, BK=16, 256 threads (8 warps, 2m x 4n).
//   A row-major (lda). B: TRANSB=false -> B[K][N] row-major (ldb);
//                      TRANSB=true  -> B[N][K] row-major (ldb) (i.e. B^T given).
//   EPI: 0=bias, 1=bias*scale, 2=gelu(bias), 3=raw (no bias)
//   ZMODE: 0=plain; 1=QK^T (per-head q,k, C=scores); 2=PV (A=probs, B=v, C=ao)
// Smem is fragment-ready: per (tile, kstep, lane) vectors for m16n8k8 frags.
// =====================================================================
template<int BN, int EPI, int ZMODE, bool TRANSB>
__global__ __launch_bounds__(256, 2) void mma_gemm(
    const float* __restrict__ A, long long lda,
    const float* __restrict__ Bg, long long ldb,
    const float* __restrict__ bias,
    float* __restrict__ C, long long ldc,
    int K, float scale)
{
    constexpr int MT = 4;            // m16 tiles per warp (warp covers 64 rows)
    constexpr int NT = BN / 32;      // n8 tiles per warp (4 warps across n)
    constexpr int ACH = 2;           // A float4 chunks per thread (128*16/4/256)
    constexpr int BCH = (BN * 16) / 4 / 256;  // 2 for BN=128, 1 for BN=64

    __shared__ float sA[2][2048];        // 128x16 fragment-ready
    __shared__ float sB[2][BN * 16];     // 16xBN fragment-ready

    const int tid  = threadIdx.x;
    const int lane = tid & 31;
    const int w    = tid >> 5;
    const int wm   = w & 1;          // 0..1
    const int wn   = w >> 1;         // 0..3
    const int m0   = blockIdx.y * 128;
    const int n0   = blockIdx.x * BN;
    const int z    = blockIdx.z;

    if (ZMODE == 1) {
        int hoff = (z >> 4) * D + (z & 15) * 64;
        A  += hoff;
        Bg += hoff;
        C  += (size_t)z * S * S;
    }
    if (ZMODE == 2) {
        int hoff = (z >> 4) * D + (z & 15) * 64;
        A  += (size_t)z * S * S;
        Bg += hoff;
        C  += hoff;
    }

    float acc[MT][NT][4] = {};
    float4 aR[ACH];
    float4 bR[BCH];

    const int ntiles = K >> 4;

    // ---- staging: global -> regs ----
    auto load_regs = [&](int k0) {
        #pragma unroll
        for (int u = 0; u < ACH; u++) {
            int cc = tid + u * 256;
            int row = cc >> 2;
            int kc  = (cc & 3) << 2;
            aR[u] = *(const float4*)(A + (size_t)(m0 + row) * lda + k0 + kc);
        }
        #pragma unroll
        for (int u = 0; u < BCH; u++) {
            int cc = tid + u * 256;
            if (TRANSB) {
                int n  = cc >> 2;
                int kc = (cc & 3) << 2;
                bR[u] = *(const float4*)(Bg + (size_t)(n0 + n) * ldb + k0 + kc);
            } else {
                int k = cc / (BN / 4);
                int n = (cc % (BN / 4)) * 4;
                bR[u] = *(const float4*)(Bg + (size_t)(k0 + k) * ldb + n0 + n);
            }
        }
    };

    // ---- staging: regs -> fragment-ready smem (with tf32 convert) ----
    auto sts = [&](int p) {
        #pragma unroll
        for (int u = 0; u < ACH; u++) {
            int cc = tid + u * 256;
            int row = cc >> 2;
            int kc  = (cc & 3) << 2;
            int mt = row >> 4, r = row & 15;
            int base = ((mt * 2 + (kc >> 3)) * 32 + ((r & 7) << 2)) * 4
                       + (r >> 3) + (((kc >> 2) & 1) << 1);
            sA[p][base +  0] = to_tf32(aR[u].x);
            sA[p][base +  4] = to_tf32(aR[u].y);
            sA[p][base +  8] = to_tf32(aR[u].z);
            sA[p][base + 12] = to_tf32(aR[u].w);
        }
        #pragma unroll
        for (int u = 0; u < BCH; u++) {
            int cc = tid + u * 256;
            if (TRANSB) {
                int n  = cc >> 2;
                int kc = (cc & 3) << 2;
                int nt = n >> 3, c8 = n & 7;
                int base = ((nt * 2 + (kc >> 3)) * 32 + (c8 << 2)) * 2 + ((kc >> 2) & 1);
                sB[p][base + 0] = to_tf32(bR[u].x);
                sB[p][base + 2] = to_tf32(bR[u].y);
                sB[p][base + 4] = to_tf32(bR[u].z);
                sB[p][base + 6] = to_tf32(bR[u].w);
            } else {
                int k = cc / (BN / 4);
                int n = (cc % (BN / 4)) * 4;
                int nt = n >> 3, cb = n & 7;
                int base = ((nt * 2 + (k >> 3)) * 32 + (cb << 2) + (k & 3)) * 2
                           + ((k >> 2) & 1);
                sB[p][base +  0] = to_tf32(bR[u].x);
                sB[p][base +  8] = to_tf32(bR[u].y);
                sB[p][base + 16] = to_tf32(bR[u].z);
                sB[p][base + 24] = to_tf32(bR[u].w);
            }
        }
    };

    // ---- compute one BK=16 tile from smem buffer p ----
    auto compute = [&](int p) {
        #pragma unroll
        for (int ks = 0; ks < 2; ks++) {
            uint32_t a[MT][4];
            uint32_t b[NT][2];
            #pragma unroll
            for (int i = 0; i < MT; i++) {
                float4 v = *(const float4*)&sA[p][(((wm * MT + i) * 2 + ks) * 32 + lane) * 4];
                a[i][0] = __float_as_uint(v.x); a[i][1] = __float_as_uint(v.y);
                a[i][2] = __float_as_uint(v.z); a[i][3] = __float_as_uint(v.w);
            }
            #pragma unroll
            for (int j = 0; j < NT; j++) {
                float2 v = *(const float2*)&sB[p][(((wn * NT + j) * 2 + ks) * 32 + lane) * 2];
                b[j][0] = __float_as_uint(v.x); b[j][1] = __float_as_uint(v.y);
            }
            #pragma unroll
            for (int i = 0; i < MT; i++)
                #pragma unroll
                for (int j = 0; j < NT; j++)
                    mma8(acc[i][j], a[i], b[j]);
        }
    };

    // ---- pipelined main loop ----
    load_regs(0);
    sts(0);
    __syncthreads();
    int p = 0;
    for (int t = 0; t < ntiles; t++) {
        bool has_next = (t + 1 < ntiles);
        if (has_next) load_regs((t + 1) << 4);
        compute(p);
        if (has_next) sts(p ^ 1);
        __syncthreads();
        p ^= 1;
    }

    // ---- epilogue ----
    #pragma unroll
    for (int i = 0; i < MT; i++) {
        int r0 = m0 + wm * 64 + i * 16 + (lane >> 2);
        #pragma unroll
        for (int j = 0; j < NT; j++) {
            int col = n0 + wn * (NT * 8) + j * 8 + ((lane & 3) << 1);
            float bx = 0.f, by = 0.f;
            if (EPI != 3) {
                float2 bb = *(const float2*)&bias[col];
                bx = bb.x; by = bb.y;
            }
            float v0 = acc[i][j][0] + bx, v1 = acc[i][j][1] + by;
            float v2 = acc[i][j][2] + bx, v3 = acc[i][j][3] + by;
            if (EPI == 1) { v0 *= scale; v1 *= scale; v2 *= scale; v3 *= scale; }
            if (EPI == 2) {
                v0 = 0.5f * v0 * (1.0f + erff(v0 * 0.70710678118654752f));
                v1 = 0.5f * v1 * (1.0f + erff(v1 * 0.70710678118654752f));
                v2 = 0.5f * v2 * (1.0f + erff(v2 * 0.70710678118654752f));
                v3 = 0.5f * v3 * (1.0f + erff(v3 * 0.70710678118654752f));
            }
            *(float2*)&C[(size_t)r0 * ldc + col]       = make_float2(v0, v1);
            *(float2*)&C[(size_t)(r0 + 8) * ldc + col] = make_float2(v2, v3);
        }
    }
}

// ---------------- softmax over last axis (+key padding mask) ----------------
__global__ __launch_bounds__(256) void softmax_kernel(
    const float* __restrict__ in, const unsigned char* __restrict__ mask,
    float* __restrict__ out)
{
    const size_t row = blockIdx.x;
    const int n = (int)(row >> 11);    // / S
    const int b = n >> 4;              // / H
    const float* ip = in + row * (size_t)S;
    float* op = out + row * (size_t)S;
    const int tid = threadIdx.x;

    float vals[8];
    float mx = -3.4e38f;
    #pragma unroll
    for (int i = 0; i < 8; i++) {
        int idx = tid + (i << 8);
        float mterm = mask[(size_t)b * S + idx] ? NEGV : 0.0f;
        float v = ip[idx] + mterm;
        vals[i] = v;
        mx = fmaxf(mx, v);
    }
    __shared__ float sh[256];
    sh[tid] = mx;
    __syncthreads();
    for (int st = 128; st > 0; st >>= 1) {
        if (tid < st) sh[tid] = fmaxf(sh[tid], sh[tid + st]);
        __syncthreads();
    }
    mx = sh[0];
    __syncthreads();

    float sum = 0.0f;
    #pragma unroll
    for (int i = 0; i < 8; i++) {
        vals[i] = __expf(vals[i] - mx);
        sum += vals[i];
    }
    sh[tid] = sum;
    __syncthreads();
    for (int st = 128; st > 0; st >>= 1) {
        if (tid < st) sh[tid] += sh[tid + st];
        __syncthreads();
    }
    float inv = 1.0f / sh[0];
    #pragma unroll
    for (int i = 0; i < 8; i++)
        op[tid + (i << 8)] = vals[i] * inv;
}

// ---------------- layernorm(resid + y) * g + beta, rows of D=1024 ----------------
__global__ __launch_bounds__(256) void ln_kernel(
    const float* __restrict__ resid, const float* __restrict__ y,
    const float* __restrict__ g, const float* __restrict__ beta,
    float* __restrict__ out)
{
    const int row = blockIdx.x;
    const int tid = threadIdx.x;
    float4 a = ((const float4*)(resid + (size_t)row * D))[tid];
    float4 c = ((const float4*)(y + (size_t)row * D))[tid];
    float v0 = a.x + c.x, v1 = a.y + c.y, v2 = a.z + c.z, v3 = a.w + c.w;

    __shared__ float sh[256], sh2[256];
    sh[tid]  = v0 + v1 + v2 + v3;
    sh2[tid] = v0*v0 + v1*v1 + v2*v2 + v3*v3;
    __syncthreads();
    for (int st = 128; st > 0; st >>= 1) {
        if (tid < st) { sh[tid] += sh[tid + st]; sh2[tid] += sh2[tid + st]; }
        __syncthreads();
    }
    float mean = sh[0] * (1.0f / D);
    float var  = sh2[0] * (1.0f / D) - mean * mean;
    float rstd = rsqrtf(var + 1e-5f);

    float4 g4 = ((const float4*)g)[tid];
    float4 b4 = ((const float4*)beta)[tid];
    float4 o;
    o.x = (v0 - mean) * rstd * g4.x + b4.x;
    o.y = (v1 - mean) * rstd * g4.y + b4.y;
    o.z = (v2 - mean) * rstd * g4.z + b4.z;
    o.w = (v3 - mean) * rstd * g4.w + b4.w;
    ((float4*)(out + (size_t)row * D))[tid] = o;
}

// ---------------- launcher ----------------
extern "C" void kernel_launch(void* const* d_in, const int* in_sizes, int n_in,
                              void* d_out, int out_size)
{
    const float* x    = (const float*)d_in[0];
    const unsigned char* mask = (const unsigned char*)d_in[1];
    const float* Wq   = (const float*)d_in[2];
    const float* bq   = (const float*)d_in[3];
    const float* Wk   = (const float*)d_in[4];
    const float* bk   = (const float*)d_in[5];
    const float* Wv   = (const float*)d_in[6];
    const float* bv   = (const float*)d_in[7];
    const float* Wo   = (const float*)d_in[8];
    const float* bo   = (const float*)d_in[9];
    const float* ln1g = (const float*)d_in[10];
    const float* ln1b = (const float*)d_in[11];
    const float* W1   = (const float*)d_in[12];
    const float* b1   = (const float*)d_in[13];
    const float* W2   = (const float*)d_in[14];
    const float* b2   = (const float*)d_in[15];
    const float* ln2g = (const float*)d_in[16];
    const float* ln2b = (const float*)d_in[17];

    float *q, *k, *v, *ao, *x1, *y, *h, *attn;
    cudaGetSymbolAddress((void**)&q,  g_q);
    cudaGetSymbolAddress((void**)&k,  g_k);
    cudaGetSymbolAddress((void**)&v,  g_v);
    cudaGetSymbolAddress((void**)&ao, g_ao);
    cudaGetSymbolAddress((void**)&x1, g_x1);
    cudaGetSymbolAddress((void**)&y,  g_y);
    cudaGetSymbolAddress((void**)&h,  g_h);
    cudaGetSymbolAddress((void**)&attn, g_attn);

    const long long X  = (long long)T * D;
    const long long AW = (long long)BATCH * H * (long long)S * S;
    float* xout;
    float* attnout;
    if ((long long)out_size >= X + AW) {
        xout = (float*)d_out;
        attnout = (float*)d_out + X;
    } else if ((long long)out_size == AW) {
        attnout = (float*)d_out;
        xout = ao;
    } else {
        xout = (float*)d_out;
        attnout = attn;
    }

    dim3 blk(256);
    const float scaling = 0.125f;   // hd^-0.5, hd=64

    // QKV projections: M=4096, N=1024, K=1024
    mma_gemm<128,1,0,false><<<dim3(D/128, T/128), blk>>>(x, D, Wq, D, bq, q, D, D, scaling);
    mma_gemm<128,0,0,false><<<dim3(D/128, T/128), blk>>>(x, D, Wk, D, bk, k, D, D, 1.0f);
    mma_gemm<128,0,0,false><<<dim3(D/128, T/128), blk>>>(x, D, Wv, D, bv, v, D, D, 1.0f);

    // QK^T per head: M=S, N=S, K=64; A=q (lda=B*D), B=k^T (n-major, ldb=B*D)
    mma_gemm<128,3,1,true><<<dim3(S/128, S/128, BATCH*H), blk>>>(
        q, (long long)BATCH*D, k, (long long)BATCH*D, nullptr, attn, S, 64, 1.0f);

    // softmax (+mask), writes attn_weights output
    softmax_kernel<<<dim3(BATCH*H*S), blk>>>(attn, mask, attnout);

    // P @ V per head: M=S, N=64, K=S
    mma_gemm<64,3,2,false><<<dim3(1, S/128, BATCH*H), blk>>>(
        attnout, S, v, (long long)BATCH*D, nullptr, ao, (long long)BATCH*D, S, 1.0f);

    // output projection + residual LN1
    mma_gemm<128,0,0,false><<<dim3(D/128, T/128), blk>>>(ao, D, Wo, D, bo, y, D, D, 1.0f);
    ln_kernel<<<dim3(T), blk>>>(x, y, ln1g, ln1b, x1);

    // FFN + residual LN2
    mma_gemm<128,2,0,false><<<dim3(FFN_DIM/128, T/128), blk>>>(x1, D, W1, FFN_DIM, b1, h, FFN_DIM, D, 1.0f);
    mma_gemm<128,0,0,false><<<dim3(D/128, T/128), blk>>>(h, FFN_DIM, W2, D, b2, y, D, FFN_DIM, 1.0f);
    ln_kernel<<<dim3(T), blk>>>(x1, y, ln2g, ln2b, xout);
}

// round 3
// speedup vs baseline: 2.5237x; 2.1857x over previous
#include <cuda_runtime.h>
#include <math.h>
#include <stdint.h>

#define S 2048
#define BATCH 2
#define D 1024
#define H 16
#define FFN_DIM 4096
#define T (S*BATCH)          // 4096 token rows
#define NEGV -1e9f

// ---------------- scratch (device globals; no allocation allowed) ----------------
__device__ float g_q[(size_t)T*D];
__device__ float g_k[(size_t)T*D];
__device__ float g_v[(size_t)T*D];
__device__ float g_ao[(size_t)T*D];
__device__ float g_x1[(size_t)T*D];
__device__ float g_y[(size_t)T*D];
__device__ float g_h[(size_t)T*FFN_DIM];
__device__ float g_attn[(size_t)BATCH*H*S*S];   // raw scores

// ---------------- tf32 helpers ----------------
__device__ __forceinline__ float to_tf32(float x) {
    uint32_t u;
    asm("cvt.rna.tf32.f32 %0, %1;" : "=r"(u) : "f"(x));
    return __uint_as_float(u);
}

__device__ __forceinline__ void mma8(float* c, const uint32_t* a, const uint32_t* b) {
    asm("mma.sync.aligned.m16n8k8.row.col.f32.tf32.tf32.f32 "
        "{%0,%1,%2,%3},{%4,%5,%6,%7},{%8,%9},{%0,%1,%2,%3};"
        : "+f"(c[0]), "+f"(c[1]), "+f"(c[2]), "+f"(c[3])
        : "r"(a[0]), "r"(a[1]), "r"(a[2]), "r"(a[3]),
          "r"(b[0]), "r"(b[1]));
}

// =====================================================================
// tf32 MMA GEMM: C[M,N] = A[M,K] @ B[K,N] (+bias, epilogue)
//   BM=128, BN in {128,64}, BK=16, 256 threads (8 warps, 2m x 4n).
//   Conflict-free smem layouts:
//     sA[row][col^((row>>1)&3)<<2], pitch 16  (STS.128 in, scalar LDS out)
//     sB[k][ (n ^ ((k>>2)&3)<<3) ], pitch BN+8
//   EPI: 0=bias, 1=bias*scale, 2=gelu(bias), 3=raw
//   ZMODE: 0=plain; 1=QK^T per-head; 2=PV per-head
// =====================================================================
template<int BN, int EPI, int ZMODE, bool TRANSB>
__global__ __launch_bounds__(256, 2) void mma_gemm(
    const float* __restrict__ A, long long lda,
    const float* __restrict__ Bg, long long ldb,
    const float* __restrict__ bias,
    float* __restrict__ C, long long ldc,
    int K, float scale)
{
    constexpr int MT = 4;
    constexpr int NT = BN / 32;
    constexpr int ACH = 2;
    constexpr int BCH = (BN * 16) / 4 / 256;  // 2 for BN=128, 1 for BN=64
    constexpr int PB  = BN + 8;               // pitch ≡ 8 (mod 32)

    __shared__ float sA[2][128 * 16];
    __shared__ float sB[2][16 * PB];

    const int tid  = threadIdx.x;
    const int lane = tid & 31;
    const int w    = tid >> 5;
    const int wm   = w & 1;
    const int wn   = w >> 1;
    const int m0   = blockIdx.y * 128;
    const int n0   = blockIdx.x * BN;
    const int z    = blockIdx.z;

    if (ZMODE == 1) {
        int hoff = (z >> 4) * D + (z & 15) * 64;
        A  += hoff;
        Bg += hoff;
        C  += (size_t)z * S * S;
    }
    if (ZMODE == 2) {
        int hoff = (z >> 4) * D + (z & 15) * 64;
        A  += (size_t)z * S * S;
        Bg += hoff;
        C  += hoff;
    }

    float acc[MT][NT][4] = {};
    float4 aR[ACH];
    float4 bR[BCH];

    const int ntiles = K >> 4;

    // ---- staging: global -> regs (coalesced float4) ----
    auto load_regs = [&](int k0) {
        #pragma unroll
        for (int u = 0; u < ACH; u++) {
            int cc = tid + u * 256;
            int row = cc >> 2;
            int kc  = (cc & 3) << 2;
            aR[u] = *(const float4*)(A + (size_t)(m0 + row) * lda + k0 + kc);
        }
        #pragma unroll
        for (int u = 0; u < BCH; u++) {
            int cc = tid + u * 256;
            if (TRANSB) {
                int n  = cc >> 2;
                int kc = (cc & 3) << 2;
                bR[u] = *(const float4*)(Bg + (size_t)(n0 + n) * ldb + k0 + kc);
            } else {
                int k = cc / (BN / 4);
                int n = (cc % (BN / 4)) * 4;
                bR[u] = *(const float4*)(Bg + (size_t)(k0 + k) * ldb + n0 + n);
            }
        }
    };

    // ---- staging: regs -> swizzled smem (tf32 convert) ----
    auto sts = [&](int p) {
        #pragma unroll
        for (int u = 0; u < ACH; u++) {
            int cc = tid + u * 256;
            int row = cc >> 2;
            int kc  = (cc & 3) << 2;
            int sa  = ((row >> 1) & 3) << 2;
            float4 t;
            t.x = to_tf32(aR[u].x); t.y = to_tf32(aR[u].y);
            t.z = to_tf32(aR[u].z); t.w = to_tf32(aR[u].w);
            *(float4*)&sA[p][row * 16 + (kc ^ sa)] = t;
        }
        #pragma unroll
        for (int u = 0; u < BCH; u++) {
            int cc = tid + u * 256;
            if (TRANSB) {
                int n  = cc >> 2;
                int kc = (cc & 3) << 2;
                float vv[4] = {bR[u].x, bR[u].y, bR[u].z, bR[u].w};
                #pragma unroll
                for (int j = 0; j < 4; j++) {
                    int k = kc + j;
                    int wk = ((k >> 2) & 3) << 3;
                    sB[p][k * PB + (n ^ wk)] = to_tf32(vv[j]);
                }
            } else {
                int k  = cc / (BN / 4);
                int n4 = (cc % (BN / 4)) * 4;
                int wk = ((k >> 2) & 3) << 3;
                float4 t;
                t.x = to_tf32(bR[u].x); t.y = to_tf32(bR[u].y);
                t.z = to_tf32(bR[u].z); t.w = to_tf32(bR[u].w);
                *(float4*)&sB[p][k * PB + (n4 ^ wk)] = t;
            }
        }
    };

    // ---- compute one BK=16 tile from smem buffer p ----
    auto compute = [&](int p) {
        #pragma unroll
        for (int ks = 0; ks < 2; ks++) {
            uint32_t a[MT][4];
            uint32_t b[NT][2];
            const int c0 = (lane & 3) + 8 * ks;
            #pragma unroll
            for (int i = 0; i < MT; i++) {
                int r0 = wm * 64 + i * 16 + (lane >> 2);
                int r1 = r0 + 8;
                int s0 = ((r0 >> 1) & 3) << 2;
                int s1 = ((r1 >> 1) & 3) << 2;
                a[i][0] = __float_as_uint(sA[p][r0 * 16 + (c0 ^ s0)]);
                a[i][1] = __float_as_uint(sA[p][r1 * 16 + (c0 ^ s1)]);
                a[i][2] = __float_as_uint(sA[p][r0 * 16 + ((c0 + 4) ^ s0)]);
                a[i][3] = __float_as_uint(sA[p][r1 * 16 + ((c0 + 4) ^ s1)]);
            }
            #pragma unroll
            for (int j = 0; j < NT; j++) {
                int k0 = c0;
                int k1 = c0 + 4;
                int n  = wn * (NT * 8) + j * 8 + (lane >> 2);
                int w0 = ((k0 >> 2) & 3) << 3;
                int w1 = ((k1 >> 2) & 3) << 3;
                b[j][0] = __float_as_uint(sB[p][k0 * PB + (n ^ w0)]);
                b[j][1] = __float_as_uint(sB[p][k1 * PB + (n ^ w1)]);
            }
            #pragma unroll
            for (int i = 0; i < MT; i++)
                #pragma unroll
                for (int j = 0; j < NT; j++)
                    mma8(acc[i][j], a[i], b[j]);
        }
    };

    // ---- pipelined main loop ----
    load_regs(0);
    sts(0);
    __syncthreads();
    int p = 0;
    for (int t = 0; t < ntiles; t++) {
        bool has_next = (t + 1 < ntiles);
        if (has_next) load_regs((t + 1) << 4);
        compute(p);
        if (has_next) sts(p ^ 1);
        __syncthreads();
        p ^= 1;
    }

    // ---- epilogue ----
    #pragma unroll
    for (int i = 0; i < MT; i++) {
        int r0 = m0 + wm * 64 + i * 16 + (lane >> 2);
        #pragma unroll
        for (int j = 0; j < NT; j++) {
            int col = n0 + wn * (NT * 8) + j * 8 + ((lane & 3) << 1);
            float bx = 0.f, by = 0.f;
            if (EPI != 3) {
                float2 bb = *(const float2*)&bias[col];
                bx = bb.x; by = bb.y;
            }
            float v0 = acc[i][j][0] + bx, v1 = acc[i][j][1] + by;
            float v2 = acc[i][j][2] + bx, v3 = acc[i][j][3] + by;
            if (EPI == 1) { v0 *= scale; v1 *= scale; v2 *= scale; v3 *= scale; }
            if (EPI == 2) {
                v0 = 0.5f * v0 * (1.0f + erff(v0 * 0.70710678118654752f));
                v1 = 0.5f * v1 * (1.0f + erff(v1 * 0.70710678118654752f));
                v2 = 0.5f * v2 * (1.0f + erff(v2 * 0.70710678118654752f));
                v3 = 0.5f * v3 * (1.0f + erff(v3 * 0.70710678118654752f));
            }
            *(float2*)&C[(size_t)r0 * ldc + col]       = make_float2(v0, v1);
            *(float2*)&C[(size_t)(r0 + 8) * ldc + col] = make_float2(v2, v3);
        }
    }
}

// ---------------- softmax over last axis (+key padding mask) ----------------
__global__ __launch_bounds__(256) void softmax_kernel(
    const float* __restrict__ in, const unsigned char* __restrict__ mask,
    float* __restrict__ out)
{
    const size_t row = blockIdx.x;
    const int n = (int)(row >> 11);
    const int b = n >> 4;
    const float* ip = in + row * (size_t)S;
    float* op = out + row * (size_t)S;
    const int tid = threadIdx.x;

    float vals[8];
    float mx = -3.4e38f;
    #pragma unroll
    for (int i = 0; i < 8; i++) {
        int idx = tid + (i << 8);
        float mterm = mask[(size_t)b * S + idx] ? NEGV : 0.0f;
        float v = ip[idx] + mterm;
        vals[i] = v;
        mx = fmaxf(mx, v);
    }
    __shared__ float sh[256];
    sh[tid] = mx;
    __syncthreads();
    for (int st = 128; st > 0; st >>= 1) {
        if (tid < st) sh[tid] = fmaxf(sh[tid], sh[tid + st]);
        __syncthreads();
    }
    mx = sh[0];
    __syncthreads();

    float sum = 0.0f;
    #pragma unroll
    for (int i = 0; i < 8; i++) {
        vals[i] = __expf(vals[i] - mx);
        sum += vals[i];
    }
    sh[tid] = sum;
    __syncthreads();
    for (int st = 128; st > 0; st >>= 1) {
        if (tid < st) sh[tid] += sh[tid + st];
        __syncthreads();
    }
    float inv = 1.0f / sh[0];
    #pragma unroll
    for (int i = 0; i < 8; i++)
        op[tid + (i << 8)] = vals[i] * inv;
}

// ---------------- layernorm(resid + y) * g + beta, rows of D=1024 ----------------
__global__ __launch_bounds__(256) void ln_kernel(
    const float* __restrict__ resid, const float* __restrict__ y,
    const float* __restrict__ g, const float* __restrict__ beta,
    float* __restrict__ out)
{
    const int row = blockIdx.x;
    const int tid = threadIdx.x;
    float4 a = ((const float4*)(resid + (size_t)row * D))[tid];
    float4 c = ((const float4*)(y + (size_t)row * D))[tid];
    float v0 = a.x + c.x, v1 = a.y + c.y, v2 = a.z + c.z, v3 = a.w + c.w;

    __shared__ float sh[256], sh2[256];
    sh[tid]  = v0 + v1 + v2 + v3;
    sh2[tid] = v0*v0 + v1*v1 + v2*v2 + v3*v3;
    __syncthreads();
    for (int st = 128; st > 0; st >>= 1) {
        if (tid < st) { sh[tid] += sh[tid + st]; sh2[tid] += sh2[tid + st]; }
        __syncthreads();
    }
    float mean = sh[0] * (1.0f / D);
    float var  = sh2[0] * (1.0f / D) - mean * mean;
    float rstd = rsqrtf(var + 1e-5f);

    float4 g4 = ((const float4*)g)[tid];
    float4 b4 = ((const float4*)beta)[tid];
    float4 o;
    o.x = (v0 - mean) * rstd * g4.x + b4.x;
    o.y = (v1 - mean) * rstd * g4.y + b4.y;
    o.z = (v2 - mean) * rstd * g4.z + b4.z;
    o.w = (v3 - mean) * rstd * g4.w + b4.w;
    ((float4*)(out + (size_t)row * D))[tid] = o;
}

// ---------------- launcher ----------------
extern "C" void kernel_launch(void* const* d_in, const int* in_sizes, int n_in,
                              void* d_out, int out_size)
{
    const float* x    = (const float*)d_in[0];
    const unsigned char* mask = (const unsigned char*)d_in[1];
    const float* Wq   = (const float*)d_in[2];
    const float* bq   = (const float*)d_in[3];
    const float* Wk   = (const float*)d_in[4];
    const float* bk   = (const float*)d_in[5];
    const float* Wv   = (const float*)d_in[6];
    const float* bv   = (const float*)d_in[7];
    const float* Wo   = (const float*)d_in[8];
    const float* bo   = (const float*)d_in[9];
    const float* ln1g = (const float*)d_in[10];
    const float* ln1b = (const float*)d_in[11];
    const float* W1   = (const float*)d_in[12];
    const float* b1   = (const float*)d_in[13];
    const float* W2   = (const float*)d_in[14];
    const float* b2   = (const float*)d_in[15];
    const float* ln2g = (const float*)d_in[16];
    const float* ln2b = (const float*)d_in[17];

    float *q, *k, *v, *ao, *x1, *y, *h, *attn;
    cudaGetSymbolAddress((void**)&q,  g_q);
    cudaGetSymbolAddress((void**)&k,  g_k);
    cudaGetSymbolAddress((void**)&v,  g_v);
    cudaGetSymbolAddress((void**)&ao, g_ao);
    cudaGetSymbolAddress((void**)&x1, g_x1);
    cudaGetSymbolAddress((void**)&y,  g_y);
    cudaGetSymbolAddress((void**)&h,  g_h);
    cudaGetSymbolAddress((void**)&attn, g_attn);

    const long long X  = (long long)T * D;
    const long long AW = (long long)BATCH * H * (long long)S * S;
    float* xout;
    float* attnout;
    if ((long long)out_size >= X + AW) {
        xout = (float*)d_out;
        attnout = (float*)d_out + X;
    } else if ((long long)out_size == AW) {
        attnout = (float*)d_out;
        xout = ao;
    } else {
        xout = (float*)d_out;
        attnout = attn;
    }

    dim3 blk(256);
    const float scaling = 0.125f;   // hd^-0.5, hd=64

    // QKV projections: M=4096, N=1024, K=1024
    mma_gemm<128,1,0,false><<<dim3(D/128, T/128), blk>>>(x, D, Wq, D, bq, q, D, D, scaling);
    mma_gemm<128,0,0,false><<<dim3(D/128, T/128), blk>>>(x, D, Wk, D, bk, k, D, D, 1.0f);
    mma_gemm<128,0,0,false><<<dim3(D/128, T/128), blk>>>(x, D, Wv, D, bv, v, D, D, 1.0f);

    // QK^T per head: M=S, N=S, K=64
    mma_gemm<128,3,1,true><<<dim3(S/128, S/128, BATCH*H), blk>>>(
        q, (long long)BATCH*D, k, (long long)BATCH*D, nullptr, attn, S, 64, 1.0f);

    // softmax (+mask), writes attn_weights output
    softmax_kernel<<<dim3(BATCH*H*S), blk>>>(attn, mask, attnout);

    // P @ V per head: M=S, N=64, K=S
    mma_gemm<64,3,2,false><<<dim3(1, S/128, BATCH*H), blk>>>(
        attnout, S, v, (long long)BATCH*D, nullptr, ao, (long long)BATCH*D, S, 1.0f);

    // output projection + residual LN1
    mma_gemm<128,0,0,false><<<dim3(D/128, T/128), blk>>>(ao, D, Wo, D, bo, y, D, D, 1.0f);
    ln_kernel<<<dim3(T), blk>>>(x, y, ln1g, ln1b, x1);

    // FFN + residual LN2
    mma_gemm<128,2,0,false><<<dim3(FFN_DIM/128, T/128), blk>>>(x1, D, W1, FFN_DIM, b1, h, FFN_DIM, D, 1.0f);
    mma_gemm<128,0,0,false><<<dim3(D/128, T/128), blk>>>(h, FFN_DIM, W2, D, b2, y, D, FFN_DIM, 1.0f);
    ln_kernel<<<dim3(T), blk>>>(x1, y, ln2g, ln2b, xout);
}

// round 4
// speedup vs baseline: 2.6745x; 1.0598x over previous
#include <cuda_runtime.h>
#include <math.h>
#include <stdint.h>

#define S 2048
#define BATCH 2
#define D 1024
#define H 16
#define FFN_DIM 4096
#define T (S*BATCH)          // 4096 token rows
#define NEGV -1e9f

// ---------------- scratch (device globals; no allocation allowed) ----------------
__device__ float g_q[(size_t)T*D];
__device__ float g_k[(size_t)T*D];
__device__ float g_v[(size_t)T*D];
__device__ float g_ao[(size_t)T*D];
__device__ float g_x1[(size_t)T*D];
__device__ float g_y[(size_t)T*D];
__device__ float g_h[(size_t)T*FFN_DIM];
__device__ float g_attn[(size_t)BATCH*H*S*S];   // raw scores

// ---------------- tf32 / mma / ldmatrix helpers ----------------
__device__ __forceinline__ float to_tf32(float x) {
    uint32_t u;
    asm("cvt.rna.tf32.f32 %0, %1;" : "=r"(u) : "f"(x));
    return __uint_as_float(u);
}

__device__ __forceinline__ void mma8(float* c, const uint32_t* a, const uint32_t* b) {
    asm("mma.sync.aligned.m16n8k8.row.col.f32.tf32.tf32.f32 "
        "{%0,%1,%2,%3},{%4,%5,%6,%7},{%8,%9},{%0,%1,%2,%3};"
        : "+f"(c[0]), "+f"(c[1]), "+f"(c[2]), "+f"(c[3])
        : "r"(a[0]), "r"(a[1]), "r"(a[2]), "r"(a[3]),
          "r"(b[0]), "r"(b[1]));
}

__device__ __forceinline__ void ldsm4(uint32_t& r0, uint32_t& r1, uint32_t& r2, uint32_t& r3,
                                      uint32_t addr) {
    asm volatile("ldmatrix.sync.aligned.m8n8.x4.shared.b16 {%0,%1,%2,%3}, [%4];"
                 : "=r"(r0), "=r"(r1), "=r"(r2), "=r"(r3) : "r"(addr));
}

// chunk index (in floats) for (row, kword-group kq): conflict-free both for
// STS.128 staging phases and ldmatrix 8-row phases (verified per 8-lane phase).
__device__ __forceinline__ int chidx(int row, int kq) {
    return (row * 4 + (kq ^ ((row >> 1) & 3))) * 4;
}

// =====================================================================
// tf32 MMA GEMM: C[M,N] = A[M,K] @ B[K,N] (+bias, epilogue)
//   BM=128, BN in {128,64}, BK=16, 256 threads (8 warps, 2m x 4n).
//   Both A and B staged into 16B-chunk swizzled smem, fragments via ldmatrix.
//   EPI: 0=bias, 1=bias*scale, 2=gelu(bias), 3=raw
//   ZMODE: 0=plain; 1=QK^T per-head; 2=PV per-head
// =====================================================================
template<int BN, int EPI, int ZMODE, bool TRANSB>
__global__ __launch_bounds__(256, 2) void mma_gemm(
    const float* __restrict__ A, long long lda,
    const float* __restrict__ Bg, long long ldb,
    const float* __restrict__ bias,
    float* __restrict__ C, long long ldc,
    int K, float scale)
{
    constexpr int MT = 4;
    constexpr int NT = BN / 32;
    constexpr int ACH = 2;            // A float4 chunks per thread
    constexpr int BCH = BN / 64;      // B float4 chunks per thread

    __shared__ float sA[2][128 * 16];
    __shared__ float sB[2][BN * 16];

    const int tid  = threadIdx.x;
    const int lane = tid & 31;
    const int w    = tid >> 5;
    const int wm   = w & 1;
    const int wn   = w >> 1;
    const int m0   = blockIdx.y * 128;
    const int n0   = blockIdx.x * BN;
    const int z    = blockIdx.z;

    if (ZMODE == 1) {
        int hoff = (z >> 4) * D + (z & 15) * 64;
        A  += hoff;
        Bg += hoff;
        C  += (size_t)z * S * S;
    }
    if (ZMODE == 2) {
        int hoff = (z >> 4) * D + (z & 15) * 64;
        A  += (size_t)z * S * S;
        Bg += hoff;
        C  += hoff;
    }

    float acc[MT][NT][4] = {};
    float4 aR[ACH];
    float4 bR[BCH];

    const int ntiles = K >> 4;

    // lane-invariant fragment geometry
    const int fm  = lane >> 3;            // matrix id 0..3
    const int fj  = lane & 7;             // row-within-matrix
    const int aRowBase = wm * 64 + (fm & 1) * 8 + fj;   // + i*16
    const int aKqOff   = fm >> 1;                        // + ks*2
    const int bTileOff = fm >> 1;                        // + wn*NT + j2
    const int bKqOff   = fm & 1;                         // + ks*2
    const int bRowIn   = fj;

    uint32_t sA_u32[2], sB_u32[2];
    sA_u32[0] = (uint32_t)__cvta_generic_to_shared(&sA[0][0]);
    sA_u32[1] = (uint32_t)__cvta_generic_to_shared(&sA[1][0]);
    sB_u32[0] = (uint32_t)__cvta_generic_to_shared(&sB[0][0]);
    sB_u32[1] = (uint32_t)__cvta_generic_to_shared(&sB[1][0]);

    // ---- staging: global -> regs (coalesced) ----
    auto load_regs = [&](int k0) {
        #pragma unroll
        for (int u = 0; u < ACH; u++) {
            int cc = tid + u * 256;
            int row = cc >> 2;
            int kq  = cc & 3;
            aR[u] = *(const float4*)(A + (size_t)(m0 + row) * lda + k0 + kq * 4);
        }
        #pragma unroll
        for (int u = 0; u < BCH; u++) {
            int cc = tid + u * 256;
            if (TRANSB) {
                int n  = cc >> 2;
                int kq = cc & 3;
                bR[u] = *(const float4*)(Bg + (size_t)(n0 + n) * ldb + k0 + kq * 4);
            } else {
                int n  = cc & (BN - 1);
                int kq = cc / BN;
                const float* bp = Bg + (size_t)(k0 + kq * 4) * ldb + n0 + n;
                bR[u].x = bp[0];
                bR[u].y = bp[ldb];
                bR[u].z = bp[2 * ldb];
                bR[u].w = bp[3 * ldb];
            }
        }
    };

    // ---- staging: regs -> swizzled smem (tf32 convert), STS.128 conflict-free ----
    auto sts = [&](int p) {
        #pragma unroll
        for (int u = 0; u < ACH; u++) {
            int cc = tid + u * 256;
            int row = cc >> 2;
            int kq  = cc & 3;
            float4 t;
            t.x = to_tf32(aR[u].x); t.y = to_tf32(aR[u].y);
            t.z = to_tf32(aR[u].z); t.w = to_tf32(aR[u].w);
            *(float4*)&sA[p][chidx(row, kq)] = t;
        }
        #pragma unroll
        for (int u = 0; u < BCH; u++) {
            int cc = tid + u * 256;
            int n, kq;
            if (TRANSB) { n = cc >> 2; kq = cc & 3; }
            else        { n = cc & (BN - 1); kq = cc / BN; }
            float4 t;
            t.x = to_tf32(bR[u].x); t.y = to_tf32(bR[u].y);
            t.z = to_tf32(bR[u].z); t.w = to_tf32(bR[u].w);
            *(float4*)&sB[p][chidx(n, kq)] = t;
        }
    };

    // ---- compute one BK=16 tile from smem buffer p (fragments via ldmatrix) ----
    auto compute = [&](int p) {
        #pragma unroll
        for (int ks = 0; ks < 2; ks++) {
            uint32_t a[MT][4];
            uint32_t b[NT][2];
            const int akq = ks * 2 + aKqOff;
            const int bkq = ks * 2 + bKqOff;
            #pragma unroll
            for (int i = 0; i < MT; i++) {
                uint32_t addr = sA_u32[p] + (uint32_t)(chidx(aRowBase + i * 16, akq) * 4);
                ldsm4(a[i][0], a[i][1], a[i][2], a[i][3], addr);
            }
            #pragma unroll
            for (int j2 = 0; j2 < NT; j2 += 2) {
                int tile = wn * NT + j2 + bTileOff;
                uint32_t addr = sB_u32[p] + (uint32_t)(chidx(tile * 8 + bRowIn, bkq) * 4);
                ldsm4(b[j2][0], b[j2][1], b[j2 + 1][0], b[j2 + 1][1], addr);
            }
            #pragma unroll
            for (int i = 0; i < MT; i++)
                #pragma unroll
                for (int j = 0; j < NT; j++)
                    mma8(acc[i][j], a[i], b[j]);
        }
    };

    // ---- pipelined main loop ----
    load_regs(0);
    sts(0);
    __syncthreads();
    int p = 0;
    for (int t = 0; t < ntiles; t++) {
        bool has_next = (t + 1 < ntiles);
        if (has_next) load_regs((t + 1) << 4);
        compute(p);
        if (has_next) sts(p ^ 1);
        __syncthreads();
        p ^= 1;
    }

    // ---- epilogue ----
    #pragma unroll
    for (int i = 0; i < MT; i++) {
        int r0 = m0 + wm * 64 + i * 16 + (lane >> 2);
        #pragma unroll
        for (int j = 0; j < NT; j++) {
            int col = n0 + wn * (NT * 8) + j * 8 + ((lane & 3) << 1);
            float bx = 0.f, by = 0.f;
            if (EPI != 3) {
                float2 bb = *(const float2*)&bias[col];
                bx = bb.x; by = bb.y;
            }
            float v0 = acc[i][j][0] + bx, v1 = acc[i][j][1] + by;
            float v2 = acc[i][j][2] + bx, v3 = acc[i][j][3] + by;
            if (EPI == 1) { v0 *= scale; v1 *= scale; v2 *= scale; v3 *= scale; }
            if (EPI == 2) {
                v0 = 0.5f * v0 * (1.0f + erff(v0 * 0.70710678118654752f));
                v1 = 0.5f * v1 * (1.0f + erff(v1 * 0.70710678118654752f));
                v2 = 0.5f * v2 * (1.0f + erff(v2 * 0.70710678118654752f));
                v3 = 0.5f * v3 * (1.0f + erff(v3 * 0.70710678118654752f));
            }
            *(float2*)&C[(size_t)r0 * ldc + col]       = make_float2(v0, v1);
            *(float2*)&C[(size_t)(r0 + 8) * ldc + col] = make_float2(v2, v3);
        }
    }
}

// ---------------- softmax over last axis (+key padding mask) ----------------
__global__ __launch_bounds__(256) void softmax_kernel(
    const float* __restrict__ in, const unsigned char* __restrict__ mask,
    float* __restrict__ out)
{
    const size_t row = blockIdx.x;
    const int n = (int)(row >> 11);
    const int b = n >> 4;
    const float* ip = in + row * (size_t)S;
    float* op = out + row * (size_t)S;
    const int tid = threadIdx.x;

    float vals[8];
    float mx = -3.4e38f;
    #pragma unroll
    for (int i = 0; i < 8; i++) {
        int idx = tid + (i << 8);
        float mterm = mask[(size_t)b * S + idx] ? NEGV : 0.0f;
        float v = ip[idx] + mterm;
        vals[i] = v;
        mx = fmaxf(mx, v);
    }
    __shared__ float sh[256];
    sh[tid] = mx;
    __syncthreads();
    for (int st = 128; st > 0; st >>= 1) {
        if (tid < st) sh[tid] = fmaxf(sh[tid], sh[tid + st]);
        __syncthreads();
    }
    mx = sh[0];
    __syncthreads();

    float sum = 0.0f;
    #pragma unroll
    for (int i = 0; i < 8; i++) {
        vals[i] = __expf(vals[i] - mx);
        sum += vals[i];
    }
    sh[tid] = sum;
    __syncthreads();
    for (int st = 128; st > 0; st >>= 1) {
        if (tid < st) sh[tid] += sh[tid + st];
        __syncthreads();
    }
    float inv = 1.0f / sh[0];
    #pragma unroll
    for (int i = 0; i < 8; i++)
        op[tid + (i << 8)] = vals[i] * inv;
}

// ---------------- layernorm(resid + y) * g + beta, rows of D=1024 ----------------
__global__ __launch_bounds__(256) void ln_kernel(
    const float* __restrict__ resid, const float* __restrict__ y,
    const float* __restrict__ g, const float* __restrict__ beta,
    float* __restrict__ out)
{
    const int row = blockIdx.x;
    const int tid = threadIdx.x;
    float4 a = ((const float4*)(resid + (size_t)row * D))[tid];
    float4 c = ((const float4*)(y + (size_t)row * D))[tid];
    float v0 = a.x + c.x, v1 = a.y + c.y, v2 = a.z + c.z, v3 = a.w + c.w;

    __shared__ float sh[256], sh2[256];
    sh[tid]  = v0 + v1 + v2 + v3;
    sh2[tid] = v0*v0 + v1*v1 + v2*v2 + v3*v3;
    __syncthreads();
    for (int st = 128; st > 0; st >>= 1) {
        if (tid < st) { sh[tid] += sh[tid + st]; sh2[tid] += sh2[tid + st]; }
        __syncthreads();
    }
    float mean = sh[0] * (1.0f / D);
    float var  = sh2[0] * (1.0f / D) - mean * mean;
    float rstd = rsqrtf(var + 1e-5f);

    float4 g4 = ((const float4*)g)[tid];
    float4 b4 = ((const float4*)beta)[tid];
    float4 o;
    o.x = (v0 - mean) * rstd * g4.x + b4.x;
    o.y = (v1 - mean) * rstd * g4.y + b4.y;
    o.z = (v2 - mean) * rstd * g4.z + b4.z;
    o.w = (v3 - mean) * rstd * g4.w + b4.w;
    ((float4*)(out + (size_t)row * D))[tid] = o;
}

// ---------------- launcher ----------------
extern "C" void kernel_launch(void* const* d_in, const int* in_sizes, int n_in,
                              void* d_out, int out_size)
{
    const float* x    = (const float*)d_in[0];
    const unsigned char* mask = (const unsigned char*)d_in[1];
    const float* Wq   = (const float*)d_in[2];
    const float* bq   = (const float*)d_in[3];
    const float* Wk   = (const float*)d_in[4];
    const float* bk   = (const float*)d_in[5];
    const float* Wv   = (const float*)d_in[6];
    const float* bv   = (const float*)d_in[7];
    const float* Wo   = (const float*)d_in[8];
    const float* bo   = (const float*)d_in[9];
    const float* ln1g = (const float*)d_in[10];
    const float* ln1b = (const float*)d_in[11];
    const float* W1   = (const float*)d_in[12];
    const float* b1   = (const float*)d_in[13];
    const float* W2   = (const float*)d_in[14];
    const float* b2   = (const float*)d_in[15];
    const float* ln2g = (const float*)d_in[16];
    const float* ln2b = (const float*)d_in[17];

    float *q, *k, *v, *ao, *x1, *y, *h, *attn;
    cudaGetSymbolAddress((void**)&q,  g_q);
    cudaGetSymbolAddress((void**)&k,  g_k);
    cudaGetSymbolAddress((void**)&v,  g_v);
    cudaGetSymbolAddress((void**)&ao, g_ao);
    cudaGetSymbolAddress((void**)&x1, g_x1);
    cudaGetSymbolAddress((void**)&y,  g_y);
    cudaGetSymbolAddress((void**)&h,  g_h);
    cudaGetSymbolAddress((void**)&attn, g_attn);

    const long long X  = (long long)T * D;
    const long long AW = (long long)BATCH * H * (long long)S * S;
    float* xout;
    float* attnout;
    if ((long long)out_size >= X + AW) {
        xout = (float*)d_out;
        attnout = (float*)d_out + X;
    } else if ((long long)out_size == AW) {
        attnout = (float*)d_out;
        xout = ao;
    } else {
        xout = (float*)d_out;
        attnout = attn;
    }

    dim3 blk(256);
    const float scaling = 0.125f;   // hd^-0.5, hd=64

    // QKV projections: M=4096, N=1024, K=1024
    mma_gemm<128,1,0,false><<<dim3(D/128, T/128), blk>>>(x, D, Wq, D, bq, q, D, D, scaling);
    mma_gemm<128,0,0,false><<<dim3(D/128, T/128), blk>>>(x, D, Wk, D, bk, k, D, D, 1.0f);
    mma_gemm<128,0,0,false><<<dim3(D/128, T/128), blk>>>(x, D, Wv, D, bv, v, D, D, 1.0f);

    // QK^T per head: M=S, N=S, K=64
    mma_gemm<128,3,1,true><<<dim3(S/128, S/128, BATCH*H), blk>>>(
        q, (long long)BATCH*D, k, (long long)BATCH*D, nullptr, attn, S, 64, 1.0f);

    // softmax (+mask), writes attn_weights output
    softmax_kernel<<<dim3(BATCH*H*S), blk>>>(attn, mask, attnout);

    // P @ V per head: M=S, N=64, K=S
    mma_gemm<64,3,2,false><<<dim3(1, S/128, BATCH*H), blk>>>(
        attnout, S, v, (long long)BATCH*D, nullptr, ao, (long long)BATCH*D, S, 1.0f);

    // output projection + residual LN1
    mma_gemm<128,0,0,false><<<dim3(D/128, T/128), blk>>>(ao, D, Wo, D, bo, y, D, D, 1.0f);
    ln_kernel<<<dim3(T), blk>>>(x, y, ln1g, ln1b, x1);

    // FFN + residual LN2
    mma_gemm<128,2,0,false><<<dim3(FFN_DIM/128, T/128), blk>>>(x1, D, W1, FFN_DIM, b1, h, FFN_DIM, D, 1.0f);
    mma_gemm<128,0,0,false><<<dim3(D/128, T/128), blk>>>(h, FFN_DIM, W2, D, b2, y, D, FFN_DIM, 1.0f);
    ln_kernel<<<dim3(T), blk>>>(x1, y, ln2g, ln2b, xout);
}

// round 5
// speedup vs baseline: 3.1850x; 1.1909x over previous
#include <cuda_runtime.h>
#include <math.h>
#include <stdint.h>

#define S 2048
#define BATCH 2
#define D 1024
#define H 16
#define FFN_DIM 4096
#define T (S*BATCH)
#define NEGV -1e9f

// ---------------- scratch (device globals; no allocation allowed) ----------------
__device__ float g_q[(size_t)T*D];
__device__ float g_k[(size_t)T*D];
__device__ float g_v[(size_t)T*D];
__device__ float g_ao[(size_t)T*D];
__device__ float g_x1[(size_t)T*D];
__device__ float g_x1r[(size_t)T*D];
__device__ float g_y[(size_t)T*D];
__device__ float g_h[(size_t)T*FFN_DIM];
__device__ float g_attn[(size_t)BATCH*H*S*S];
__device__ float g_xr[(size_t)T*D];
__device__ float g_wqt[(size_t)D*D];
__device__ float g_wkt[(size_t)D*D];
__device__ float g_wvt[(size_t)D*D];
__device__ float g_wot[(size_t)D*D];
__device__ float g_w1t[(size_t)D*FFN_DIM];
__device__ float g_w2t[(size_t)D*FFN_DIM];

// ---------------- helpers ----------------
__device__ __forceinline__ float to_tf32(float x) {
    uint32_t u;
    asm("cvt.rna.tf32.f32 %0, %1;" : "=r"(u) : "f"(x));
    return __uint_as_float(u);
}

__device__ __forceinline__ void mma8(float* c, const uint32_t* a, const uint32_t* b) {
    asm("mma.sync.aligned.m16n8k8.row.col.f32.tf32.tf32.f32 "
        "{%0,%1,%2,%3},{%4,%5,%6,%7},{%8,%9},{%0,%1,%2,%3};"
        : "+f"(c[0]), "+f"(c[1]), "+f"(c[2]), "+f"(c[3])
        : "r"(a[0]), "r"(a[1]), "r"(a[2]), "r"(a[3]),
          "r"(b[0]), "r"(b[1]));
}

__device__ __forceinline__ void ldsm4(uint32_t& r0, uint32_t& r1, uint32_t& r2, uint32_t& r3,
                                      uint32_t addr) {
    asm volatile("ldmatrix.sync.aligned.m8n8.x4.shared.b16 {%0,%1,%2,%3}, [%4];"
                 : "=r"(r0), "=r"(r1), "=r"(r2), "=r"(r3) : "r"(addr));
}

__device__ __forceinline__ void cpasync16(uint32_t dst, const float* src) {
    asm volatile("cp.async.cg.shared.global [%0], [%1], 16;" :: "r"(dst), "l"(src));
}

// chunk index (in floats) for (row, kword-group kq): conflict-free for
// STS/cp.async 16B phases and ldmatrix 8-row phases.
__device__ __forceinline__ int chidx(int row, int kq) {
    return (row * 4 + (kq ^ ((row >> 1) & 3))) * 4;
}

__device__ __forceinline__ float gelu(float v) {
    return 0.5f * v * (1.0f + erff(v * 0.70710678118654752f));
}

// =====================================================================
// cp.async 3-stage tf32 GEMM. BM=128, BN=128, BK=16, 256 threads.
// A[M,K] row-major (values already tf32-rounded).
// B given N-major, k-contiguous: B[n][k] (pre-transposed weights, or k in QK^T).
// EPI: 0=bias, 1=bias*scale, 2=gelu(bias), 3=raw.  ZMODE: 0 plain, 1 QK^T.
// ROUND: round outputs to tf32 on store.
// =====================================================================
template<int EPI, int ZMODE, bool ROUND>
__global__ __launch_bounds__(256, 2) void mma_gemm_ca(
    const float* __restrict__ A, long long lda,
    const float* __restrict__ Bg, long long ldb,
    const float* __restrict__ bias,
    float* __restrict__ C, long long ldc,
    int K, float scale)
{
    constexpr int MT = 4, NT = 4, STG = 3;

    __shared__ float sA[STG][2048];
    __shared__ float sB[STG][2048];

    const int tid  = threadIdx.x;
    const int lane = tid & 31;
    const int w    = tid >> 5;
    const int wm   = w & 1;
    const int wn   = w >> 1;
    const int m0   = blockIdx.y * 128;
    const int n0   = blockIdx.x * 128;
    const int z    = blockIdx.z;

    if (ZMODE == 1) {
        int hoff = (z >> 4) * D + (z & 15) * 64;
        A  += hoff;
        Bg += hoff;
        C  += (size_t)z * S * S;
    }

    float acc[MT][NT][4] = {};

    const int ntiles = K >> 4;

    // fragment geometry
    const int fm = lane >> 3;
    const int fj = lane & 7;
    const int aRowBase = wm * 64 + (fm & 1) * 8 + fj;
    const int aKqOff   = fm >> 1;
    const int bTileOff = fm >> 1;
    const int bKqOff   = fm & 1;

    const uint32_t sA0 = (uint32_t)__cvta_generic_to_shared(&sA[0][0]);
    const uint32_t sB0 = (uint32_t)__cvta_generic_to_shared(&sB[0][0]);

    // per-thread staging coords (2 chunks each for A and B)
    const int sRow0 = tid >> 2,  sKq = tid & 3;       // chunk 0: rows 0..63
    const int sRow1 = sRow0 + 64;                     // chunk 1: rows 64..127

    auto issue = [&](int t) {
        if (t < ntiles) {
            const int buf = t % STG;
            const int k0  = t << 4;
            const uint32_t aBase = sA0 + buf * 8192;
            const uint32_t bBase = sB0 + buf * 8192;
            cpasync16(aBase + (uint32_t)(chidx(sRow0, sKq) * 4),
                      A + (size_t)(m0 + sRow0) * lda + k0 + sKq * 4);
            cpasync16(aBase + (uint32_t)(chidx(sRow1, sKq) * 4),
                      A + (size_t)(m0 + sRow1) * lda + k0 + sKq * 4);
            cpasync16(bBase + (uint32_t)(chidx(sRow0, sKq) * 4),
                      Bg + (size_t)(n0 + sRow0) * ldb + k0 + sKq * 4);
            cpasync16(bBase + (uint32_t)(chidx(sRow1, sKq) * 4),
                      Bg + (size_t)(n0 + sRow1) * ldb + k0 + sKq * 4);
        }
        asm volatile("cp.async.commit_group;");
    };

    auto compute = [&](int buf) {
        const uint32_t aBase = sA0 + buf * 8192;
        const uint32_t bBase = sB0 + buf * 8192;
        #pragma unroll
        for (int ks = 0; ks < 2; ks++) {
            uint32_t a[MT][4];
            uint32_t b[NT][2];
            const int akq = ks * 2 + aKqOff;
            const int bkq = ks * 2 + bKqOff;
            #pragma unroll
            for (int i = 0; i < MT; i++) {
                uint32_t addr = aBase + (uint32_t)(chidx(aRowBase + i * 16, akq) * 4);
                ldsm4(a[i][0], a[i][1], a[i][2], a[i][3], addr);
            }
            #pragma unroll
            for (int j2 = 0; j2 < NT; j2 += 2) {
                int tile = wn * NT + j2 + bTileOff;
                uint32_t addr = bBase + (uint32_t)(chidx(tile * 8 + fj, bkq) * 4);
                ldsm4(b[j2][0], b[j2][1], b[j2 + 1][0], b[j2 + 1][1], addr);
            }
            #pragma unroll
            for (int i = 0; i < MT; i++)
                #pragma unroll
                for (int j = 0; j < NT; j++)
                    mma8(acc[i][j], a[i], b[j]);
        }
    };

    issue(0);
    issue(1);
    for (int t = 0; t < ntiles; t++) {
        asm volatile("cp.async.wait_group 1;");
        __syncthreads();
        issue(t + 2);
        compute(t % STG);
    }

    // ---- epilogue ----
    #pragma unroll
    for (int i = 0; i < MT; i++) {
        int r0 = m0 + wm * 64 + i * 16 + (lane >> 2);
        #pragma unroll
        for (int j = 0; j < NT; j++) {
            int col = n0 + wn * 32 + j * 8 + ((lane & 3) << 1);
            float bx = 0.f, by = 0.f;
            if (EPI != 3) {
                float2 bb = *(const float2*)&bias[col];
                bx = bb.x; by = bb.y;
            }
            float v0 = acc[i][j][0] + bx, v1 = acc[i][j][1] + by;
            float v2 = acc[i][j][2] + bx, v3 = acc[i][j][3] + by;
            if (EPI == 1) { v0 *= scale; v1 *= scale; v2 *= scale; v3 *= scale; }
            if (EPI == 2) { v0 = gelu(v0); v1 = gelu(v1); v2 = gelu(v2); v3 = gelu(v3); }
            if (ROUND) {
                v0 = to_tf32(v0); v1 = to_tf32(v1);
                v2 = to_tf32(v2); v3 = to_tf32(v3);
            }
            *(float2*)&C[(size_t)r0 * ldc + col]       = make_float2(v0, v1);
            *(float2*)&C[(size_t)(r0 + 8) * ldc + col] = make_float2(v2, v3);
        }
    }
}

// =====================================================================
// Register-staging cvt GEMM (round-4 path) — used only for PV (A=probs
// needs rna conversion). BN=64, A row-major, B[K,N] row-major.
// Rounds ao outputs to tf32 (consumed by O-proj cp.async GEMM).
// =====================================================================
__global__ __launch_bounds__(256, 2) void mma_gemm_pv(
    const float* __restrict__ A, long long lda,
    const float* __restrict__ Bg, long long ldb,
    float* __restrict__ C, long long ldc, int K)
{
    constexpr int BN = 64, MT = 4, NT = 2;

    __shared__ float sA[2][128 * 16];
    __shared__ float sB[2][BN * 16];

    const int tid  = threadIdx.x;
    const int lane = tid & 31;
    const int w    = tid >> 5;
    const int wm   = w & 1;
    const int wn   = w >> 1;
    const int m0   = blockIdx.y * 128;
    const int z    = blockIdx.z;

    {
        int hoff = (z >> 4) * D + (z & 15) * 64;
        A += (size_t)z * S * S;
        Bg += hoff;
        C  += hoff;
    }

    float acc[MT][NT][4] = {};
    float4 aR[2];
    float4 bR[1];

    const int ntiles = K >> 4;

    const int fm = lane >> 3;
    const int fj = lane & 7;
    const int aRowBase = wm * 64 + (fm & 1) * 8 + fj;
    const int aKqOff   = fm >> 1;
    const int bTileOff = fm >> 1;
    const int bKqOff   = fm & 1;

    uint32_t sA_u32[2], sB_u32[2];
    sA_u32[0] = (uint32_t)__cvta_generic_to_shared(&sA[0][0]);
    sA_u32[1] = (uint32_t)__cvta_generic_to_shared(&sA[1][0]);
    sB_u32[0] = (uint32_t)__cvta_generic_to_shared(&sB[0][0]);
    sB_u32[1] = (uint32_t)__cvta_generic_to_shared(&sB[1][0]);

    auto load_regs = [&](int k0) {
        #pragma unroll
        for (int u = 0; u < 2; u++) {
            int cc = tid + u * 256;
            int row = cc >> 2;
            int kq  = cc & 3;
            aR[u] = *(const float4*)(A + (size_t)(m0 + row) * lda + k0 + kq * 4);
        }
        {
            int n  = tid & (BN - 1);
            int kq = tid / BN;
            const float* bp = Bg + (size_t)(k0 + kq * 4) * ldb + n;
            bR[0].x = bp[0];
            bR[0].y = bp[ldb];
            bR[0].z = bp[2 * ldb];
            bR[0].w = bp[3 * ldb];
        }
    };

    auto sts = [&](int p) {
        #pragma unroll
        for (int u = 0; u < 2; u++) {
            int cc = tid + u * 256;
            int row = cc >> 2;
            int kq  = cc & 3;
            float4 t;
            t.x = to_tf32(aR[u].x); t.y = to_tf32(aR[u].y);
            t.z = to_tf32(aR[u].z); t.w = to_tf32(aR[u].w);
            *(float4*)&sA[p][chidx(row, kq)] = t;
        }
        {
            int n  = tid & (BN - 1);
            int kq = tid / BN;
            float4 t;
            t.x = to_tf32(bR[0].x); t.y = to_tf32(bR[0].y);
            t.z = to_tf32(bR[0].z); t.w = to_tf32(bR[0].w);
            *(float4*)&sB[p][chidx(n, kq)] = t;
        }
    };

    auto compute = [&](int p) {
        #pragma unroll
        for (int ks = 0; ks < 2; ks++) {
            uint32_t a[MT][4];
            uint32_t b[NT][2];
            const int akq = ks * 2 + aKqOff;
            const int bkq = ks * 2 + bKqOff;
            #pragma unroll
            for (int i = 0; i < MT; i++) {
                uint32_t addr = sA_u32[p] + (uint32_t)(chidx(aRowBase + i * 16, akq) * 4);
                ldsm4(a[i][0], a[i][1], a[i][2], a[i][3], addr);
            }
            {
                int tile = wn * NT + bTileOff;
                uint32_t addr = sB_u32[p] + (uint32_t)(chidx(tile * 8 + fj, bkq) * 4);
                ldsm4(b[0][0], b[0][1], b[1][0], b[1][1], addr);
            }
            #pragma unroll
            for (int i = 0; i < MT; i++)
                #pragma unroll
                for (int j = 0; j < NT; j++)
                    mma8(acc[i][j], a[i], b[j]);
        }
    };

    load_regs(0);
    sts(0);
    __syncthreads();
    int p = 0;
    for (int t = 0; t < ntiles; t++) {
        bool has_next = (t + 1 < ntiles);
        if (has_next) load_regs((t + 1) << 4);
        compute(p);
        if (has_next) sts(p ^ 1);
        __syncthreads();
        p ^= 1;
    }

    #pragma unroll
    for (int i = 0; i < MT; i++) {
        int r0 = m0 + wm * 64 + i * 16 + (lane >> 2);
        #pragma unroll
        for (int j = 0; j < NT; j++) {
            int col = wn * 16 + j * 8 + ((lane & 3) << 1);
            float v0 = to_tf32(acc[i][j][0]), v1 = to_tf32(acc[i][j][1]);
            float v2 = to_tf32(acc[i][j][2]), v3 = to_tf32(acc[i][j][3]);
            *(float2*)&C[(size_t)r0 * ldc + col]       = make_float2(v0, v1);
            *(float2*)&C[(size_t)(r0 + 8) * ldc + col] = make_float2(v2, v3);
        }
    }
}

// ---------------- pre-pass: round to tf32 (float4) ----------------
__global__ __launch_bounds__(256) void round_kernel(const float* __restrict__ in,
                                                    float* __restrict__ out, int n4)
{
    int i = blockIdx.x * 256 + threadIdx.x;
    if (i < n4) {
        float4 v = ((const float4*)in)[i];
        v.x = to_tf32(v.x); v.y = to_tf32(v.y);
        v.z = to_tf32(v.z); v.w = to_tf32(v.w);
        ((float4*)out)[i] = v;
    }
}

// ---------------- pre-pass: transpose + round: out[N,K] = rna(in[K,N]^T) ----------------
__global__ __launch_bounds__(256) void transpose_round(const float* __restrict__ in,
                                                       float* __restrict__ out,
                                                       int K, int N)
{
    __shared__ float tile[32][33];
    int n = blockIdx.x * 32 + threadIdx.x;
    int k = blockIdx.y * 32 + threadIdx.y;
    #pragma unroll
    for (int i = 0; i < 32; i += 8)
        tile[threadIdx.y + i][threadIdx.x] = in[(size_t)(k + i) * N + n];
    __syncthreads();
    int n2 = blockIdx.x * 32 + threadIdx.y;
    int k2 = blockIdx.y * 32 + threadIdx.x;
    #pragma unroll
    for (int i = 0; i < 32; i += 8)
        out[(size_t)(n2 + i) * K + k2] = to_tf32(tile[threadIdx.x][threadIdx.y + i]);
}

// ---------------- softmax over last axis (+key padding mask) ----------------
__global__ __launch_bounds__(256) void softmax_kernel(
    const float* __restrict__ in, const unsigned char* __restrict__ mask,
    float* __restrict__ out)
{
    const size_t row = blockIdx.x;
    const int n = (int)(row >> 11);
    const int b = n >> 4;
    const float* ip = in + row * (size_t)S;
    float* op = out + row * (size_t)S;
    const int tid = threadIdx.x;

    float vals[8];
    float mx = -3.4e38f;
    #pragma unroll
    for (int i = 0; i < 8; i++) {
        int idx = tid + (i << 8);
        float mterm = mask[(size_t)b * S + idx] ? NEGV : 0.0f;
        float v = ip[idx] + mterm;
        vals[i] = v;
        mx = fmaxf(mx, v);
    }
    __shared__ float sh[256];
    sh[tid] = mx;
    __syncthreads();
    for (int st = 128; st > 0; st >>= 1) {
        if (tid < st) sh[tid] = fmaxf(sh[tid], sh[tid + st]);
        __syncthreads();
    }
    mx = sh[0];
    __syncthreads();

    float sum = 0.0f;
    #pragma unroll
    for (int i = 0; i < 8; i++) {
        vals[i] = __expf(vals[i] - mx);
        sum += vals[i];
    }
    sh[tid] = sum;
    __syncthreads();
    for (int st = 128; st > 0; st >>= 1) {
        if (tid < st) sh[tid] += sh[tid + st];
        __syncthreads();
    }
    float inv = 1.0f / sh[0];
    #pragma unroll
    for (int i = 0; i < 8; i++)
        op[tid + (i << 8)] = vals[i] * inv;
}

// ---------------- layernorm(resid + y) * g + beta ----------------
__global__ __launch_bounds__(256) void ln_kernel(
    const float* __restrict__ resid, const float* __restrict__ y,
    const float* __restrict__ g, const float* __restrict__ beta,
    float* __restrict__ out, float* __restrict__ out_r)
{
    const int row = blockIdx.x;
    const int tid = threadIdx.x;
    float4 a = ((const float4*)(resid + (size_t)row * D))[tid];
    float4 c = ((const float4*)(y + (size_t)row * D))[tid];
    float v0 = a.x + c.x, v1 = a.y + c.y, v2 = a.z + c.z, v3 = a.w + c.w;

    __shared__ float sh[256], sh2[256];
    sh[tid]  = v0 + v1 + v2 + v3;
    sh2[tid] = v0*v0 + v1*v1 + v2*v2 + v3*v3;
    __syncthreads();
    for (int st = 128; st > 0; st >>= 1) {
        if (tid < st) { sh[tid] += sh[tid + st]; sh2[tid] += sh2[tid + st]; }
        __syncthreads();
    }
    float mean = sh[0] * (1.0f / D);
    float var  = sh2[0] * (1.0f / D) - mean * mean;
    float rstd = rsqrtf(var + 1e-5f);

    float4 g4 = ((const float4*)g)[tid];
    float4 b4 = ((const float4*)beta)[tid];
    float4 o;
    o.x = (v0 - mean) * rstd * g4.x + b4.x;
    o.y = (v1 - mean) * rstd * g4.y + b4.y;
    o.z = (v2 - mean) * rstd * g4.z + b4.z;
    o.w = (v3 - mean) * rstd * g4.w + b4.w;
    ((float4*)(out + (size_t)row * D))[tid] = o;
    if (out_r) {
        float4 r;
        r.x = to_tf32(o.x); r.y = to_tf32(o.y);
        r.z = to_tf32(o.z); r.w = to_tf32(o.w);
        ((float4*)(out_r + (size_t)row * D))[tid] = r;
    }
}

// ---------------- launcher ----------------
extern "C" void kernel_launch(void* const* d_in, const int* in_sizes, int n_in,
                              void* d_out, int out_size)
{
    const float* x    = (const float*)d_in[0];
    const unsigned char* mask = (const unsigned char*)d_in[1];
    const float* Wq   = (const float*)d_in[2];
    const float* bq   = (const float*)d_in[3];
    const float* Wk   = (const float*)d_in[4];
    const float* bk   = (const float*)d_in[5];
    const float* Wv   = (const float*)d_in[6];
    const float* bv   = (const float*)d_in[7];
    const float* Wo   = (const float*)d_in[8];
    const float* bo   = (const float*)d_in[9];
    const float* ln1g = (const float*)d_in[10];
    const float* ln1b = (const float*)d_in[11];
    const float* W1   = (const float*)d_in[12];
    const float* b1   = (const float*)d_in[13];
    const float* W2   = (const float*)d_in[14];
    const float* b2   = (const float*)d_in[15];
    const float* ln2g = (const float*)d_in[16];
    const float* ln2b = (const float*)d_in[17];

    float *q, *k, *v, *ao, *x1, *x1r, *y, *h, *attn, *xr;
    float *wqt, *wkt, *wvt, *wot, *w1t, *w2t;
    cudaGetSymbolAddress((void**)&q,   g_q);
    cudaGetSymbolAddress((void**)&k,   g_k);
    cudaGetSymbolAddress((void**)&v,   g_v);
    cudaGetSymbolAddress((void**)&ao,  g_ao);
    cudaGetSymbolAddress((void**)&x1,  g_x1);
    cudaGetSymbolAddress((void**)&x1r, g_x1r);
    cudaGetSymbolAddress((void**)&y,   g_y);
    cudaGetSymbolAddress((void**)&h,   g_h);
    cudaGetSymbolAddress((void**)&attn, g_attn);
    cudaGetSymbolAddress((void**)&xr,  g_xr);
    cudaGetSymbolAddress((void**)&wqt, g_wqt);
    cudaGetSymbolAddress((void**)&wkt, g_wkt);
    cudaGetSymbolAddress((void**)&wvt, g_wvt);
    cudaGetSymbolAddress((void**)&wot, g_wot);
    cudaGetSymbolAddress((void**)&w1t, g_w1t);
    cudaGetSymbolAddress((void**)&w2t, g_w2t);

    const long long X  = (long long)T * D;
    const long long AW = (long long)BATCH * H * (long long)S * S;
    float* xout;
    float* attnout;
    if ((long long)out_size >= X + AW) {
        xout = (float*)d_out;
        attnout = (float*)d_out + X;
    } else if ((long long)out_size == AW) {
        attnout = (float*)d_out;
        xout = ao;
    } else {
        xout = (float*)d_out;
        attnout = attn;
    }

    dim3 blk(256);
    dim3 tb(32, 8);
    const float scaling = 0.125f;

    // ---- pre-pass: round x; transpose+round weights ----
    round_kernel<<<dim3((T*D/4 + 255)/256), blk>>>(x, xr, T*D/4);
    transpose_round<<<dim3(D/32, D/32), tb>>>(Wq, wqt, D, D);
    transpose_round<<<dim3(D/32, D/32), tb>>>(Wk, wkt, D, D);
    transpose_round<<<dim3(D/32, D/32), tb>>>(Wv, wvt, D, D);
    transpose_round<<<dim3(D/32, D/32), tb>>>(Wo, wot, D, D);
    transpose_round<<<dim3(FFN_DIM/32, D/32), tb>>>(W1, w1t, D, FFN_DIM);
    transpose_round<<<dim3(D/32, FFN_DIM/32), tb>>>(W2, w2t, FFN_DIM, D);

    // ---- QKV projections (cp.async, rounded outputs) ----
    mma_gemm_ca<1,0,true><<<dim3(D/128, T/128), blk>>>(xr, D, wqt, D, bq, q, D, D, scaling);
    mma_gemm_ca<0,0,true><<<dim3(D/128, T/128), blk>>>(xr, D, wkt, D, bk, k, D, D, 1.0f);
    mma_gemm_ca<0,0,true><<<dim3(D/128, T/128), blk>>>(xr, D, wvt, D, bv, v, D, D, 1.0f);

    // ---- QK^T per head ----
    mma_gemm_ca<3,1,false><<<dim3(S/128, S/128, BATCH*H), blk>>>(
        q, (long long)BATCH*D, k, (long long)BATCH*D, nullptr, attn, S, 64, 1.0f);

    // ---- softmax (+mask) ----
    softmax_kernel<<<dim3(BATCH*H*S), blk>>>(attn, mask, attnout);

    // ---- P @ V per head (cvt path, rounds ao) ----
    mma_gemm_pv<<<dim3(1, S/128, BATCH*H), blk>>>(
        attnout, S, v, (long long)BATCH*D, ao, (long long)BATCH*D, S);

    // ---- O-proj + LN1 ----
    mma_gemm_ca<0,0,false><<<dim3(D/128, T/128), blk>>>(ao, D, wot, D, bo, y, D, D, 1.0f);
    ln_kernel<<<dim3(T), blk>>>(x, y, ln1g, ln1b, x1, x1r);

    // ---- FFN + LN2 ----
    mma_gemm_ca<2,0,true><<<dim3(FFN_DIM/128, T/128), blk>>>(x1r, D, w1t, D, b1, h, FFN_DIM, D, 1.0f);
    mma_gemm_ca<0,0,false><<<dim3(D/128, T/128), blk>>>(h, FFN_DIM, w2t, FFN_DIM, b2, y, D, FFN_DIM, 1.0f);
    ln_kernel<<<dim3(T), blk>>>(x1, y, ln2g, ln2b, xout, nullptr);
}